// round 4
// baseline (speedup 1.0000x reference)
#include <cuda_runtime.h>
#include <cstdint>
#include <cstddef>

#define NN   100000
#define IND  128
#define HID  64
#define OUTD 128
#define ECAP 1700000

// Scratch (device globals — no allocation allowed)
__device__ __align__(16) float g_y1[(size_t)NN * HID];   // x @ w1_l
__device__ __align__(16) float g_xr[(size_t)NN * HID];   // x @ w1_r
__device__ __align__(16) float g_h [(size_t)NN * HID];   // layer-1 activations
__device__ __align__(16) float g_mh[(size_t)NN * HID];   // mean of h over neighbors
__device__ __align__(16) float g_rinv[NN];               // 1 / max(deg, 1)
__device__ int   g_deg[NN];
__device__ int   g_cur[NN];
__device__ int   g_off[NN + 1];
__device__ int   g_eidx[ECAP];                           // src node per CSR slot

// ---------------------------------------------------------------------------
// Zero degree + cursor
// ---------------------------------------------------------------------------
__global__ void k_init() {
    int i = blockIdx.x * blockDim.x + threadIdx.x;
    if (i < NN) { g_deg[i] = 0; g_cur[i] = 0; }
}

// ---------------------------------------------------------------------------
// Degree count (int atomics). edge_index is INT32 (JAX default x64-disabled).
// ---------------------------------------------------------------------------
__global__ void k_deg(const int* __restrict__ dst, int E) {
    int e = blockIdx.x * blockDim.x + threadIdx.x;
    if (e < E) {
        int d = dst[e];
        if (d >= 0 && d < NN) atomicAdd(&g_deg[d], 1);
    }
}

// ---------------------------------------------------------------------------
// Single-block exclusive scan over degrees -> g_off; also g_rinv.
// 1024 threads, each owns a contiguous chunk; Hillis-Steele over chunk sums.
// ---------------------------------------------------------------------------
__global__ __launch_bounds__(1024) void k_scan() {
    __shared__ int ssum[1024];
    const int T = 1024;
    int t = threadIdx.x;
    int chunk = (NN + T - 1) / T;
    int beg = t * chunk;
    int end = min(beg + chunk, NN);

    int s = 0;
    for (int i = beg; i < end; i++) s += g_deg[i];
    ssum[t] = s;
    __syncthreads();

    for (int d = 1; d < T; d <<= 1) {
        int v = (t >= d) ? ssum[t - d] : 0;
        __syncthreads();
        ssum[t] += v;
        __syncthreads();
    }
    int run = (t == 0) ? 0 : ssum[t - 1];

    for (int i = beg; i < end; i++) {
        int dgi = g_deg[i];
        g_off[i] = run;
        g_rinv[i] = 1.0f / fmaxf((float)dgi, 1.0f);
        run += dgi;
    }
    if (t == T - 1) g_off[NN] = run;
}

// ---------------------------------------------------------------------------
// CSR fill: slot = off[dst] + ticket; store src index.
// ---------------------------------------------------------------------------
__global__ void k_fill(const int* __restrict__ src,
                       const int* __restrict__ dst, int E) {
    int e = blockIdx.x * blockDim.x + threadIdx.x;
    if (e >= E) return;
    int d = dst[e];
    int s = src[e];
    if (d < 0 || d >= NN || s < 0 || s >= NN) return;
    int pos = g_off[d] + atomicAdd(&g_cur[d], 1);
    if (pos >= 0 && pos < ECAP) g_eidx[pos] = s;
}

// ---------------------------------------------------------------------------
// Layer-1 fused GEMM: y1 = x @ w1_l,  xr = x @ w1_r   (x:[NN,128], w:[128,64])
// j = warp*16 + lane%16 -> output column (j<64: w1_l, else w1_r);
// kh = lane/16 -> K-half, pair-reduced with shfl_xor(16).
// ---------------------------------------------------------------------------
__global__ __launch_bounds__(256) void k_gemm1(
    const float* __restrict__ x,
    const float* __restrict__ w1l,
    const float* __restrict__ w1r,
    int n)
{
    int tid  = threadIdx.x;
    int lane = tid & 31;
    int warp = tid >> 5;
    int j    = warp * 16 + (lane & 15);
    int kh   = lane >> 4;

    const float* w = (j < 64) ? w1l : w1r;
    int col = (j < 64) ? j : (j - 64);

    float wc[64];
#pragma unroll
    for (int k = 0; k < 64; k++)
        wc[k] = __ldg(&w[(size_t)(kh * 64 + k) * 64 + col]);

    for (int i = blockIdx.x; i < n; i += gridDim.x) {
        const float4* x4 = (const float4*)(x + (size_t)i * IND + kh * 64);
        float a0 = 0.f, a1 = 0.f, a2 = 0.f, a3 = 0.f;
#pragma unroll
        for (int k4 = 0; k4 < 16; k4++) {
            float4 v = __ldg(x4 + k4);
            a0 = fmaf(v.x, wc[4 * k4 + 0], a0);
            a1 = fmaf(v.y, wc[4 * k4 + 1], a1);
            a2 = fmaf(v.z, wc[4 * k4 + 2], a2);
            a3 = fmaf(v.w, wc[4 * k4 + 3], a3);
        }
        float acc = (a0 + a1) + (a2 + a3);
        acc += __shfl_xor_sync(0xffffffffu, acc, 16);
        if (kh == 0) {
            if (j < 64) g_y1[(size_t)i * HID + j]        = acc;
            else        g_xr[(size_t)i * HID + (j - 64)] = acc;
        }
    }
}

// ---------------------------------------------------------------------------
// Gather-side aggregation, one warp per node. No float atomics.
// layer 0: g_h  = relu(mean(g_y1[nbrs]) + b1 + g_xr)
// layer 1: g_mh = mean(g_h[nbrs])
// Lane c handles columns 2c, 2c+1 (float2).
// ---------------------------------------------------------------------------
__global__ __launch_bounds__(256) void k_agg(const float* __restrict__ b1,
                                             int layer)
{
    int node = blockIdx.x * 8 + (threadIdx.x >> 5);
    if (node >= NN) return;
    int lane = threadIdx.x & 31;

    const float* val = (layer == 0) ? g_y1 : g_h;
    int beg = g_off[node];
    int end = g_off[node + 1];

    float2 a0 = {0.f, 0.f}, a1 = {0.f, 0.f}, a2 = {0.f, 0.f}, a3 = {0.f, 0.f};
    int e = beg;
    for (; e + 4 <= end; e += 4) {
        int s0 = __ldg(&g_eidx[e + 0]);
        int s1 = __ldg(&g_eidx[e + 1]);
        int s2 = __ldg(&g_eidx[e + 2]);
        int s3 = __ldg(&g_eidx[e + 3]);
        float2 v0 = ((const float2*)(val + (size_t)s0 * HID))[lane];
        float2 v1 = ((const float2*)(val + (size_t)s1 * HID))[lane];
        float2 v2 = ((const float2*)(val + (size_t)s2 * HID))[lane];
        float2 v3 = ((const float2*)(val + (size_t)s3 * HID))[lane];
        a0.x += v0.x; a0.y += v0.y;
        a1.x += v1.x; a1.y += v1.y;
        a2.x += v2.x; a2.y += v2.y;
        a3.x += v3.x; a3.y += v3.y;
    }
    for (; e < end; e++) {
        int s = __ldg(&g_eidx[e]);
        float2 v = ((const float2*)(val + (size_t)s * HID))[lane];
        a0.x += v.x; a0.y += v.y;
    }
    float2 acc;
    acc.x = (a0.x + a1.x) + (a2.x + a3.x);
    acc.y = (a0.y + a1.y) + (a2.y + a3.y);

    float r = g_rinv[node];
    if (layer == 0) {
        float2 xv = ((const float2*)(g_xr + (size_t)node * HID))[lane];
        float2 bb = __ldg((const float2*)b1 + lane);
        float2 h;
        h.x = fmaxf(fmaf(acc.x, r, bb.x + xv.x), 0.f);
        h.y = fmaxf(fmaf(acc.y, r, bb.y + xv.y), 0.f);
        ((float2*)(g_h + (size_t)node * HID))[lane] = h;
    } else {
        float2 m;
        m.x = acc.x * r;
        m.y = acc.y * r;
        ((float2*)(g_mh + (size_t)node * HID))[lane] = m;
    }
}

// ---------------------------------------------------------------------------
// Layer-2 fused output: out = g_mh @ w2_l + b2 + g_h @ w2_r
// kh=0 -> mh/w2_l branch, kh=1 -> h/w2_r branch; pair-reduced via shfl.
// ---------------------------------------------------------------------------
__global__ __launch_bounds__(256) void k_out(
    const float* __restrict__ w2l,
    const float* __restrict__ w2r,
    const float* __restrict__ b2,
    float* __restrict__ out,
    int n)
{
    int tid  = threadIdx.x;
    int lane = tid & 31;
    int warp = tid >> 5;
    int j    = warp * 16 + (lane & 15);   // output column 0..127
    int kh   = lane >> 4;                 // 0: mh/w2_l, 1: h/w2_r

    const float* w = (kh == 0) ? w2l : w2r;   // [64,128]
    float wc[64];
#pragma unroll
    for (int k = 0; k < 64; k++)
        wc[k] = __ldg(&w[(size_t)k * 128 + j]);

    float bj = __ldg(b2 + j);

    for (int i = blockIdx.x; i < n; i += gridDim.x) {
        const float* srcrow = (kh == 0) ? (g_mh + (size_t)i * HID)
                                        : (g_h  + (size_t)i * HID);
        const float4* s4 = (const float4*)srcrow;
        float a0 = 0.f, a1 = 0.f, a2 = 0.f, a3 = 0.f;
#pragma unroll
        for (int k4 = 0; k4 < 16; k4++) {
            float4 v = __ldg(s4 + k4);
            a0 = fmaf(v.x, wc[4 * k4 + 0], a0);
            a1 = fmaf(v.y, wc[4 * k4 + 1], a1);
            a2 = fmaf(v.z, wc[4 * k4 + 2], a2);
            a3 = fmaf(v.w, wc[4 * k4 + 3], a3);
        }
        float acc = (a0 + a1) + (a2 + a3);
        acc += __shfl_xor_sync(0xffffffffu, acc, 16);
        if (kh == 0)
            out[(size_t)i * OUTD + j] = acc + bj;
    }
}

// ---------------------------------------------------------------------------
// Launch
// ---------------------------------------------------------------------------
extern "C" void kernel_launch(void* const* d_in, const int* in_sizes, int n_in,
                              void* d_out, int out_size) {
    const float* x   = (const float*)d_in[0];
    const int*   ei  = (const int*)d_in[1];     // int32 edge_index [2, E]
    const float* w1l = (const float*)d_in[2];
    const float* b1  = (const float*)d_in[3];
    const float* w1r = (const float*)d_in[4];
    const float* w2l = (const float*)d_in[5];
    const float* b2  = (const float*)d_in[6];
    const float* w2r = (const float*)d_in[7];
    float* out = (float*)d_out;

    int E = in_sizes[1] / 2;
    const int* src = ei;
    const int* dst = ei + E;

    // CSR build (int atomics only)
    k_init<<<(NN + 511) / 512, 512>>>();
    k_deg <<<(E + 255) / 256, 256>>>(dst, E);
    k_scan<<<1, 1024>>>();
    k_fill<<<(E + 255) / 256, 256>>>(src, dst, E);

    // Layer-1 projections
    k_gemm1<<<888, 256>>>(x, w1l, w1r, NN);

    // Aggregations (gather-side, warp per node)
    k_agg<<<(NN + 7) / 8, 256>>>(b1, 0);
    k_agg<<<(NN + 7) / 8, 256>>>(b1, 1);

    // Output GEMV
    k_out<<<888, 256>>>(w2l, w2r, b2, out, NN);
}